// round 3
// baseline (speedup 1.0000x reference)
#include <cuda_runtime.h>
#include <cstdint>
#include <math.h>

#define BB   16
#define CIN  64
#define HH   64
#define WW   64
#define HID  128
#define OC4  512   // 4*HID

typedef unsigned long long ull;

// scratch for z_is: [b][h][oc][w]
__device__ float g_z[BB * HH * OC4 * WW];
// double-buffered h state: [par][b][ic][w]
__device__ float g_h[2 * BB * HID * WW];
// progress flags: [b][rank]
__device__ int   g_flag[BB * 8];

// ---- packed fp32x2 helpers (SASS FFMA2 path, PTX-only) ----------------------
__device__ __forceinline__ ull pk2(float a, float b) {
    ull r; asm("mov.b64 %0, {%1,%2};" : "=l"(r) : "f"(a), "f"(b)); return r;
}
__device__ __forceinline__ ull dup2(float a) {
    ull r; asm("mov.b64 %0, {%1,%1};" : "=l"(r) : "f"(a)); return r;
}
__device__ __forceinline__ void ffma2(ull& d, ull a, ull b) {
    asm("fma.rn.f32x2 %0, %1, %2, %0;" : "+l"(d) : "l"(a), "l"(b));
}
__device__ __forceinline__ ull add2(ull a, ull b) {
    ull r; asm("add.rn.f32x2 %0, %1, %2;" : "=l"(r) : "l"(a), "l"(b)); return r;
}
__device__ __forceinline__ float lo32(ull a) {
    float x; asm("{ .reg .b32 t; mov.b64 {%0, t}, %1; }" : "=f"(x) : "l"(a)); return x;
}
__device__ __forceinline__ float hi32(ull a) {
    float x; asm("{ .reg .b32 t; mov.b64 {t, %0}, %1; }" : "=f"(x) : "l"(a)); return x;
}
// (hi(a), lo(b)) — the misaligned (odd) pair
__device__ __forceinline__ ull mid2(ull a, ull b) { return pk2(hi32(a), lo32(b)); }

// ----------------------------------------------------------------------------
// Kernel 0: zero h parity-0 buffer and flags (graph-replay safe init)
// ----------------------------------------------------------------------------
__global__ void init_kernel()
{
    int i = blockIdx.x * 256 + threadIdx.x;
    if (i < BB * HID * WW) g_h[i] = 0.f;          // parity 0 only
    if (i < BB * 8)        g_flag[i] = 0;
}

// ----------------------------------------------------------------------------
// Kernel 1: masked input conv (taps 0,1), FFMA2 over w-pairs.
// z[b,h,oc,w] = b_is[oc] + sum_cin ( x[b,cin,h,w-1]*w_is[oc,cin,0]
//                                  + x[b,cin,h,w  ]*w_is[oc,cin,1] )
// grid = B*H blocks, 256 threads (2 oc x 16 w per thread).
// ----------------------------------------------------------------------------
__global__ void __launch_bounds__(256)
conv_in_kernel(const float* __restrict__ x,
               const float* __restrict__ w_is,
               const float* __restrict__ b_is)
{
    extern __shared__ float smem[];
    float* xs = smem;              // [cin][68], xs[cin][w+1] = x, pads zero
    float* ws = smem + 64 * 68;    // [cin][t(2)][ocl(128)]

    int tid = threadIdx.x;
    int bh  = blockIdx.x;
    int b   = bh >> 6;
    int h   = bh & 63;

    const float* xb = x + ((long)(b * CIN) * HH + h) * WW;
    for (int i = tid; i < CIN * WW; i += 256) {
        int cin = i >> 6, w = i & 63;
        xs[cin * 68 + w + 1] = xb[(long)cin * HH * WW + w];
    }
    if (tid < 64) {
        xs[tid * 68 + 0]  = 0.f;
        xs[tid * 68 + 65] = 0.f;
        xs[tid * 68 + 66] = 0.f;
        xs[tid * 68 + 67] = 0.f;
    }
    __syncthreads();

    int wb  = tid & 3;        // w-block of 16
    int ocl = tid >> 2;       // 0..63
    int w0  = wb * 16;

    for (int p = 0; p < 4; p++) {
        int ocbase = p * 128;
        for (int i = tid; i < 128 * 192; i += 256) {
            int ol = i / 192, r = i % 192;
            int cin = r / 3, t = r % 3;
            float v = w_is[(long)(ocbase + ol) * 192 + r];
            if (t < 2) ws[(cin * 2 + t) * 128 + ol] = v;
        }
        __syncthreads();

        ull acc0[8], acc1[8];
        ull bb0 = dup2(b_is[ocbase + ocl]);
        ull bb1 = dup2(b_is[ocbase + ocl + 64]);
#pragma unroll
        for (int k = 0; k < 8; k++) { acc0[k] = bb0; acc1[k] = bb1; }

#pragma unroll 2
        for (int cin = 0; cin < 64; cin++) {
            ull d00 = dup2(ws[(cin * 2 + 0) * 128 + ocl]);
            ull d01 = dup2(ws[(cin * 2 + 1) * 128 + ocl]);
            ull d10 = dup2(ws[(cin * 2 + 0) * 128 + ocl + 64]);
            ull d11 = dup2(ws[(cin * 2 + 1) * 128 + ocl + 64]);

            const float* xrow = &xs[cin * 68 + w0];
            ull A[9];
            ulonglong2 q0 = *(const ulonglong2*)(xrow);
            ulonglong2 q1 = *(const ulonglong2*)(xrow + 4);
            ulonglong2 q2 = *(const ulonglong2*)(xrow + 8);
            ulonglong2 q3 = *(const ulonglong2*)(xrow + 12);
            A[0] = q0.x; A[1] = q0.y; A[2] = q1.x; A[3] = q1.y;
            A[4] = q2.x; A[5] = q2.y; A[6] = q3.x; A[7] = q3.y;
            A[8] = *(const ull*)(xrow + 16);

            ull op[8];
#pragma unroll
            for (int k = 0; k < 8; k++) op[k] = mid2(A[k], A[k + 1]);

#pragma unroll
            for (int k = 0; k < 8; k++) {
                ffma2(acc0[k], A[k],  d00);
                ffma2(acc0[k], op[k], d01);
                ffma2(acc1[k], A[k],  d10);
                ffma2(acc1[k], op[k], d11);
            }
        }

        float* z0 = &g_z[((long)bh * OC4 + ocbase + ocl)      * WW + w0];
        float* z1 = &g_z[((long)bh * OC4 + ocbase + ocl + 64) * WW + w0];
#pragma unroll
        for (int k = 0; k < 4; k++) {
            *(ulonglong2*)&z0[4 * k] = make_ulonglong2(acc0[2 * k], acc0[2 * k + 1]);
            *(ulonglong2*)&z1[4 * k] = make_ulonglong2(acc1[2 * k], acc1[2 * k + 1]);
        }
        __syncthreads();
    }
}

// ----------------------------------------------------------------------------
// Kernel 2: sequential row scan, FFMA2. 8 CTAs per batch, 128 threads/CTA.
// Thread = 2 channels (l0=2*lp, l1=2*lp+1) x 16 w. Weights resident in smem.
// h exchanged via double-buffered global + flag sync (one wave, co-resident).
// ----------------------------------------------------------------------------
__global__ void __launch_bounds__(128)
scan_kernel(const float* __restrict__ w_ss,
            const float* __restrict__ b_ss,
            float* __restrict__ out)
{
    extern __shared__ float smem[];
    float* Wsm  = smem;                    // [(ic*3+t)][64 l]   24576 floats
    float* hs   = Wsm + 128 * 3 * 64;      // [128 ic][68]        8704 floats
    float* zbuf = hs + 128 * 68;           // [64 l][64 w]        4096 floats
    float* cs   = zbuf + 64 * 64;          // [16 hcl][64 w]      1024 floats

    int tid  = threadIdx.x;
    int rank = blockIdx.x & 7;
    int b    = blockIdx.x >> 3;

    // stage recurrent weights: Wsm[(ic*3+t)*64 + l] = w_ss[ocg(l)][ic][t]
    for (int i = tid; i < 128 * 3 * 64; i += 128) {
        int ic = i / 192, r = i % 192;
        int t = r >> 6, l = r & 63;
        int ocg = (l >> 4) * 128 + rank * 16 + (l & 15);
        Wsm[(ic * 3 + t) * 64 + l] = w_ss[((long)ocg * 128 + ic) * 3 + t];
    }
    // zero h pads (persist across rows) and c state
    {
        int ic = tid;                      // 128 threads, 128 rows
        hs[ic * 68 + 0]  = 0.f;
        hs[ic * 68 + 65] = 0.f;
        hs[ic * 68 + 66] = 0.f;
        hs[ic * 68 + 67] = 0.f;
    }
    for (int i = tid; i < 16 * 64; i += 128) cs[i] = 0.f;
    __syncthreads();

    int wb = tid & 3;
    int lp = tid >> 2;          // 0..31
    int l0 = lp * 2;
    int l1 = lp * 2 + 1;
    int w0 = wb * 16;
    int ocg0 = (l0 >> 4) * 128 + rank * 16 + (l0 & 15);
    int ocg1 = (l1 >> 4) * 128 + rank * 16 + (l1 & 15);
    ull bias0 = dup2(b_ss[ocg0]);
    ull bias1 = dup2(b_ss[ocg1]);

    volatile int* flags = g_flag + b * 8;

    for (int row = 0; row < HH; row++) {
        int par  = row & 1;
        int par1 = par ^ 1;

        // load full h (parity par) into padded smem
        const float4* gh4 = (const float4*)&g_h[((long)par * BB + b) * HID * WW];
        for (int i = tid; i < 2048; i += 128) {        // float4 index
            int ic = i >> 4, w = (i & 15) * 4;
            float4 v = gh4[i];
            float* d = &hs[ic * 68 + w + 1];
            d[0] = v.x; d[1] = v.y; d[2] = v.z; d[3] = v.w;
        }
        __syncthreads();

        // acc = z_is + bias (packed pairs over w)
        ull acc0[8], acc1[8];
        {
            const ulonglong2* zp0 = (const ulonglong2*)&g_z[(((long)b * HH + row) * OC4 + ocg0) * WW + w0];
            const ulonglong2* zp1 = (const ulonglong2*)&g_z[(((long)b * HH + row) * OC4 + ocg1) * WW + w0];
#pragma unroll
            for (int q = 0; q < 4; q++) {
                ulonglong2 v0 = zp0[q];
                ulonglong2 v1 = zp1[q];
                acc0[2 * q]     = add2(v0.x, bias0);
                acc0[2 * q + 1] = add2(v0.y, bias0);
                acc1[2 * q]     = add2(v1.x, bias1);
                acc1[2 * q + 1] = add2(v1.y, bias1);
            }
        }

        // recurrent conv: acc[w] += sum_ic,t h[ic][w+t] * W[l][ic][t]
#pragma unroll 2
        for (int ic = 0; ic < 128; ic++) {
            const float2* wp = (const float2*)&Wsm[(ic * 3) * 64 + l0];
            float2 wt0 = wp[0];            // (W[l0][t0], W[l1][t0])
            float2 wt1 = wp[32];           // +64 floats
            float2 wt2 = wp[64];           // +128 floats
            ull w00 = dup2(wt0.x), w10 = dup2(wt0.y);
            ull w01 = dup2(wt1.x), w11 = dup2(wt1.y);
            ull w02 = dup2(wt2.x), w12 = dup2(wt2.y);

            const float* hrow = &hs[ic * 68 + w0];
            ull A[9];
            ulonglong2 q0 = *(const ulonglong2*)(hrow);
            ulonglong2 q1 = *(const ulonglong2*)(hrow + 4);
            ulonglong2 q2 = *(const ulonglong2*)(hrow + 8);
            ulonglong2 q3 = *(const ulonglong2*)(hrow + 12);
            A[0] = q0.x; A[1] = q0.y; A[2] = q1.x; A[3] = q1.y;
            A[4] = q2.x; A[5] = q2.y; A[6] = q3.x; A[7] = q3.y;
            A[8] = *(const ull*)(hrow + 16);

            ull op[8];
#pragma unroll
            for (int k = 0; k < 8; k++) op[k] = mid2(A[k], A[k + 1]);

#pragma unroll
            for (int k = 0; k < 8; k++) {
                ffma2(acc0[k], A[k],     w00);
                ffma2(acc0[k], op[k],    w01);
                ffma2(acc0[k], A[k + 1], w02);
                ffma2(acc1[k], A[k],     w10);
                ffma2(acc1[k], op[k],    w11);
                ffma2(acc1[k], A[k + 1], w12);
            }
        }

#pragma unroll
        for (int k = 0; k < 8; k++) {
            *(ull*)&zbuf[l0 * 64 + w0 + 2 * k] = acc0[k];
            *(ull*)&zbuf[l1 * 64 + w0 + 2 * k] = acc1[k];
        }
        __syncthreads();

        // gate math: 1024 (hcl,w) elems, 8 per thread; write out + new h
        float* ghw = &g_h[((long)par1 * BB + b) * HID * WW];
#pragma unroll
        for (int k = 0; k < 8; k++) {
            int idx = tid + k * 128;
            int hcl = idx >> 6, w = idx & 63;
            float zi  = zbuf[(0  + hcl) * 64 + w];
            float zf  = zbuf[(16 + hcl) * 64 + w];
            float zo  = zbuf[(32 + hcl) * 64 + w];
            float zg2 = zbuf[(48 + hcl) * 64 + w];
            float ig = 1.f / (1.f + expf(-zi));
            float fg = 1.f / (1.f + expf(-zf));
            float og = 1.f / (1.f + expf(-zo));
            float gg = tanhf(zg2);
            float c = fg * cs[hcl * 64 + w] + ig * gg;
            cs[hcl * 64 + w] = c;
            float hv2 = og * tanhf(c);
            int ch = rank * 16 + hcl;
            out[(((long)b * HID + ch) * HH + row) * WW + w] = hv2;
            if (row < HH - 1) ghw[ch * WW + w] = hv2;
        }

        if (row < HH - 1) {
            __threadfence();
            __syncthreads();
            if (tid == 0) flags[rank] = row + 1;
            if (tid < 8) {
                while (flags[tid] < row + 1) { }   // tight spin, L2-latency paced
            }
            __threadfence();
            __syncthreads();
        }
    }
}

// ----------------------------------------------------------------------------
extern "C" void kernel_launch(void* const* d_in, const int* in_sizes, int n_in,
                              void* d_out, int out_size)
{
    (void)in_sizes; (void)n_in; (void)out_size;
    const float* x    = (const float*)d_in[0];
    const float* w_is = (const float*)d_in[1];
    const float* b_is = (const float*)d_in[2];
    const float* w_ss = (const float*)d_in[3];
    const float* b_ss = (const float*)d_in[4];
    float* out = (float*)d_out;

    const int conv_smem = (64 * 68 + 64 * 2 * 128) * 4;                      // 82944 B
    const int scan_smem = (128 * 3 * 64 + 128 * 68 + 64 * 64 + 16 * 64) * 4; // 153600 B

    cudaFuncSetAttribute(conv_in_kernel, cudaFuncAttributeMaxDynamicSharedMemorySize, conv_smem);
    cudaFuncSetAttribute(scan_kernel,    cudaFuncAttributeMaxDynamicSharedMemorySize, scan_smem);

    init_kernel<<<(BB * HID * WW + 255) / 256, 256>>>();
    conv_in_kernel<<<BB * HH, 256, conv_smem>>>(x, w_is, b_is);
    scan_kernel<<<BB * 8, 256 / 2, scan_smem>>>(w_ss, b_ss, out);
}

// round 4
// speedup vs baseline: 1.3894x; 1.3894x over previous
#include <cuda_runtime.h>
#include <cstdint>
#include <math.h>

#define BB   16
#define CIN  64
#define HH   64
#define WW   64
#define HID  128
#define OC4  512   // 4*HID

// scratch for z_is: [b][h][oc][w]
__device__ float g_z[BB * HH * OC4 * WW];
// double-buffered h state: [par][b][ic][w]
__device__ float g_h[2 * BB * HID * WW];
// progress flags: [b][rank]
__device__ int   g_flag[BB * 8];

// ----------------------------------------------------------------------------
// Kernel 0: zero h parity-0 buffer and flags (graph-replay safe init)
// ----------------------------------------------------------------------------
__global__ void init_kernel()
{
    int i = blockIdx.x * 256 + threadIdx.x;
    if (i < BB * HID * WW) g_h[i] = 0.f;          // parity 0 only
    if (i < BB * 8)        g_flag[i] = 0;
}

// ----------------------------------------------------------------------------
// Kernel 1: masked input conv (taps 0,1 of the 1x3 kernel)
// z[b,h,oc,w] = b_is[oc] + sum_cin ( x[b,cin,h,w-1]*w_is[oc,cin,0]
//                                  + x[b,cin,h,w  ]*w_is[oc,cin,1] )
// grid = B*H blocks, 256 threads. Mapping: ocl = tid&63, wb = tid>>6
// -> x loads are warp-broadcast, weight loads conflict-free.
// ----------------------------------------------------------------------------
__global__ void __launch_bounds__(256)
conv_in_kernel(const float* __restrict__ x,
               const float* __restrict__ w_is,
               const float* __restrict__ b_is)
{
    extern __shared__ float smem[];
    float* xs = smem;              // [cin][68], xs[cin][w+1] = x, pads zero
    float* ws = smem + 64 * 68;    // [cin][t(2)][ocl(128)]

    int tid = threadIdx.x;
    int bh  = blockIdx.x;
    int b   = bh >> 6;
    int h   = bh & 63;

    const float* xb = x + ((long)(b * CIN) * HH + h) * WW;
    for (int i = tid; i < CIN * WW; i += 256) {
        int cin = i >> 6, w = i & 63;
        xs[cin * 68 + w + 1] = xb[(long)cin * HH * WW + w];
    }
    if (tid < 64) {
        xs[tid * 68 + 0]  = 0.f;
        xs[tid * 68 + 65] = 0.f;
        xs[tid * 68 + 66] = 0.f;
        xs[tid * 68 + 67] = 0.f;
    }
    __syncthreads();

    int ocl = tid & 63;       // 0..63 : lane-consecutive -> conflict-free W
    int wb  = tid >> 6;       // 0..3  : warp-uniform     -> broadcast x
    int w0  = wb * 16;

    for (int p = 0; p < 4; p++) {
        int ocbase = p * 128;
        for (int i = tid; i < 128 * 192; i += 256) {
            int ol = i / 192, r = i % 192;
            int cin = r / 3, t = r % 3;
            float v = w_is[(long)(ocbase + ol) * 192 + r];
            if (t < 2) ws[(cin * 2 + t) * 128 + ol] = v;
        }
        __syncthreads();

        float acc0[16], acc1[16];
        float bb0 = b_is[ocbase + ocl];
        float bb1 = b_is[ocbase + ocl + 64];
#pragma unroll
        for (int j = 0; j < 16; j++) { acc0[j] = bb0; acc1[j] = bb1; }

        for (int cin = 0; cin < 64; cin++) {
            float w00 = ws[(cin * 2 + 0) * 128 + ocl];
            float w01 = ws[(cin * 2 + 1) * 128 + ocl];
            float w10 = ws[(cin * 2 + 0) * 128 + ocl + 64];
            float w11 = ws[(cin * 2 + 1) * 128 + ocl + 64];
            float xv[20];
            const float4* xp = reinterpret_cast<const float4*>(&xs[cin * 68 + w0]);
            *(float4*)&xv[0]  = xp[0];
            *(float4*)&xv[4]  = xp[1];
            *(float4*)&xv[8]  = xp[2];
            *(float4*)&xv[12] = xp[3];
            *(float4*)&xv[16] = xp[4];
#pragma unroll
            for (int j = 0; j < 16; j++) {
                acc0[j] = fmaf(xv[j],     w00, acc0[j]);
                acc0[j] = fmaf(xv[j + 1], w01, acc0[j]);
                acc1[j] = fmaf(xv[j],     w10, acc1[j]);
                acc1[j] = fmaf(xv[j + 1], w11, acc1[j]);
            }
        }

        float* z0 = &g_z[((long)bh * OC4 + ocbase + ocl)      * WW + w0];
        float* z1 = &g_z[((long)bh * OC4 + ocbase + ocl + 64) * WW + w0];
#pragma unroll
        for (int j = 0; j < 16; j += 4) {
            *(float4*)&z0[j] = make_float4(acc0[j], acc0[j+1], acc0[j+2], acc0[j+3]);
            *(float4*)&z1[j] = make_float4(acc1[j], acc1[j+1], acc1[j+2], acc1[j+3]);
        }
        __syncthreads();
    }
}

// ----------------------------------------------------------------------------
// Kernel 2: sequential row scan. 8 CTAs per batch, 256 threads.
// Mapping: l = tid&63 (lane-consecutive weights), wb = tid>>6 (broadcast h).
// h exchanged via double-buffered global + flag sync (one wave, co-resident).
// ----------------------------------------------------------------------------
__global__ void __launch_bounds__(256)
scan_kernel(const float* __restrict__ w_ss,
            const float* __restrict__ b_ss,
            float* __restrict__ out)
{
    extern __shared__ float smem[];
    float* Wsm  = smem;                    // [(ic*3+t)][64 l]   24576 floats
    float* hs   = Wsm + 128 * 3 * 64;      // [128 ic][68]        8704 floats
    float* zbuf = hs + 128 * 68;           // [64 l][68 pad]      4352 floats
    float* cs   = zbuf + 64 * 68;          // [16 hcl][64 w]      1024 floats

    int tid  = threadIdx.x;
    int rank = blockIdx.x & 7;
    int b    = blockIdx.x >> 3;

    // stage recurrent weights: Wsm[(ic*3+t)*64 + l] = w_ss[ocg(l)][ic][t]
    for (int i = tid; i < 128 * 3 * 64; i += 256) {
        int ic = i / 192, r = i % 192;
        int t = r >> 6, l = r & 63;
        int ocg = (l >> 4) * 128 + rank * 16 + (l & 15);
        Wsm[(ic * 3 + t) * 64 + l] = w_ss[((long)ocg * 128 + ic) * 3 + t];
    }
    // zero h pads (persist across rows) and c state
    for (int i = tid; i < 128; i += 256) {
        hs[i * 68 + 0]  = 0.f;
        hs[i * 68 + 65] = 0.f;
        hs[i * 68 + 66] = 0.f;
        hs[i * 68 + 67] = 0.f;
    }
    for (int i = tid; i < 16 * 64; i += 256) cs[i] = 0.f;
    __syncthreads();

    int l  = tid & 63;        // 0..63: gate g = l>>4, local hid = l&15
    int wb = tid >> 6;        // 0..3 : warp-uniform
    int w0 = wb * 16;
    int ocg = (l >> 4) * 128 + rank * 16 + (l & 15);
    float bias = b_ss[ocg];

    volatile int* flags = g_flag + b * 8;

    for (int row = 0; row < HH; row++) {
        int par  = row & 1;
        int par1 = par ^ 1;

        // load full h (parity par) into padded smem
        const float4* gh4 = (const float4*)&g_h[((long)par * BB + b) * HID * WW];
        for (int i = tid; i < 2048; i += 256) {        // float4 index
            int ic = i >> 4, w = (i & 15) * 4;
            float4 v = gh4[i];
            float* d = &hs[ic * 68 + w + 1];
            d[0] = v.x; d[1] = v.y; d[2] = v.z; d[3] = v.w;
        }
        __syncthreads();

        // acc = z_is + bias
        const float* zg = &g_z[(((long)b * HH + row) * OC4 + ocg) * WW + w0];
        float acc[16];
#pragma unroll
        for (int j4 = 0; j4 < 4; j4++) {
            float4 v = *(const float4*)&zg[j4 * 4];
            acc[j4 * 4 + 0] = v.x + bias;
            acc[j4 * 4 + 1] = v.y + bias;
            acc[j4 * 4 + 2] = v.z + bias;
            acc[j4 * 4 + 3] = v.w + bias;
        }
        // recurrent conv: acc[j] += sum_ic,t h[ic][w0+j+t-1]*W[l][ic][t]
        for (int ic = 0; ic < 128; ic++) {
            float wt0 = Wsm[(ic * 3 + 0) * 64 + l];
            float wt1 = Wsm[(ic * 3 + 1) * 64 + l];
            float wt2 = Wsm[(ic * 3 + 2) * 64 + l];
            float hv[20];
            const float4* hp = (const float4*)&hs[ic * 68 + w0];  // broadcast
            *(float4*)&hv[0]  = hp[0];
            *(float4*)&hv[4]  = hp[1];
            *(float4*)&hv[8]  = hp[2];
            *(float4*)&hv[12] = hp[3];
            *(float4*)&hv[16] = hp[4];
#pragma unroll
            for (int j = 0; j < 16; j++) {
                acc[j] = fmaf(hv[j],     wt0, acc[j]);
                acc[j] = fmaf(hv[j + 1], wt1, acc[j]);
                acc[j] = fmaf(hv[j + 2], wt2, acc[j]);
            }
        }
#pragma unroll
        for (int j = 0; j < 16; j += 4)
            *(float4*)&zbuf[l * 68 + w0 + j] =
                make_float4(acc[j], acc[j+1], acc[j+2], acc[j+3]);
        __syncthreads();

        // gate math: 1024 (hcl,w) elems, 4 per thread; write out + new h
        float* ghw = &g_h[((long)par1 * BB + b) * HID * WW];
#pragma unroll
        for (int k = 0; k < 4; k++) {
            int idx = tid + k * 256;
            int hcl = idx >> 6, w = idx & 63;
            float zi  = zbuf[(0  + hcl) * 68 + w];
            float zf  = zbuf[(16 + hcl) * 68 + w];
            float zo  = zbuf[(32 + hcl) * 68 + w];
            float zg2 = zbuf[(48 + hcl) * 68 + w];
            float ig = 1.f / (1.f + expf(-zi));
            float fg = 1.f / (1.f + expf(-zf));
            float og = 1.f / (1.f + expf(-zo));
            float gg = tanhf(zg2);
            float c = fg * cs[hcl * 64 + w] + ig * gg;
            cs[hcl * 64 + w] = c;
            float hv2 = og * tanhf(c);
            int ch = rank * 16 + hcl;
            out[(((long)b * HID + ch) * HH + row) * WW + w] = hv2;
            if (row < HH - 1) ghw[ch * WW + w] = hv2;
        }

        if (row < HH - 1) {
            __threadfence();
            __syncthreads();
            if (tid == 0) flags[rank] = row + 1;
            if (tid < 8) {
                while (flags[tid] < row + 1) { }   // tight spin, L2-latency paced
            }
            __threadfence();
            __syncthreads();
        }
    }
}

// ----------------------------------------------------------------------------
extern "C" void kernel_launch(void* const* d_in, const int* in_sizes, int n_in,
                              void* d_out, int out_size)
{
    (void)in_sizes; (void)n_in; (void)out_size;
    const float* x    = (const float*)d_in[0];
    const float* w_is = (const float*)d_in[1];
    const float* b_is = (const float*)d_in[2];
    const float* w_ss = (const float*)d_in[3];
    const float* b_ss = (const float*)d_in[4];
    float* out = (float*)d_out;

    const int conv_smem = (64 * 68 + 64 * 2 * 128) * 4;                      // 82944 B
    const int scan_smem = (128 * 3 * 64 + 128 * 68 + 64 * 68 + 16 * 64) * 4; // 154624 B

    cudaFuncSetAttribute(conv_in_kernel, cudaFuncAttributeMaxDynamicSharedMemorySize, conv_smem);
    cudaFuncSetAttribute(scan_kernel,    cudaFuncAttributeMaxDynamicSharedMemorySize, scan_smem);

    init_kernel<<<(BB * HID * WW + 255) / 256, 256>>>();
    conv_in_kernel<<<BB * HH, 256, conv_smem>>>(x, w_is, b_is);
    scan_kernel<<<BB * 8, 256, scan_smem>>>(w_ss, b_ss, out);
}

// round 5
// speedup vs baseline: 1.4094x; 1.0144x over previous
#include <cuda_runtime.h>
#include <cstdint>
#include <math.h>

#define BB   16
#define CIN  64
#define HH   64
#define WW   64
#define HID  128
#define OC4  512   // 4*HID

typedef unsigned long long ull;

// scratch for z_is: [b][h][oc][w]
__device__ float g_z[BB * HH * OC4 * WW];
// double-buffered h state: [par][b][ic][w]  (row0 never read -> no init needed)
__device__ float g_h[2 * BB * HID * WW];
// monotonic progress flags: [b][rank] (never reset; base read per launch)
__device__ int   g_flag[BB * 8];

// ---- packed fp32x2 helpers (SASS FFMA2 path, PTX-only) ----------------------
__device__ __forceinline__ ull pk2(float a, float b) {
    ull r; asm("mov.b64 %0, {%1,%2};" : "=l"(r) : "f"(a), "f"(b)); return r;
}
__device__ __forceinline__ ull dup2(float a) {
    ull r; asm("mov.b64 %0, {%1,%1};" : "=l"(r) : "f"(a)); return r;
}
__device__ __forceinline__ void ffma2(ull& d, ull a, ull b) {
    asm("fma.rn.f32x2 %0, %1, %2, %0;" : "+l"(d) : "l"(a), "l"(b));
}
__device__ __forceinline__ ull add2(ull a, ull b) {
    ull r; asm("add.rn.f32x2 %0, %1, %2;" : "=l"(r) : "l"(a), "l"(b)); return r;
}
__device__ __forceinline__ float lo32(ull a) {
    float x; asm("{ .reg .b32 t; mov.b64 {%0, t}, %1; }" : "=f"(x) : "l"(a)); return x;
}
__device__ __forceinline__ float hi32(ull a) {
    float x; asm("{ .reg .b32 t; mov.b64 {t, %0}, %1; }" : "=f"(x) : "l"(a)); return x;
}

// ----------------------------------------------------------------------------
// Kernel 1: masked input conv (taps 0,1). Unchanged from R4 (known good).
// ----------------------------------------------------------------------------
__global__ void __launch_bounds__(256)
conv_in_kernel(const float* __restrict__ x,
               const float* __restrict__ w_is,
               const float* __restrict__ b_is)
{
    extern __shared__ float smem[];
    float* xs = smem;              // [cin][68], xs[cin][w+1] = x, pads zero
    float* ws = smem + 64 * 68;    // [cin][t(2)][ocl(128)]

    int tid = threadIdx.x;
    int bh  = blockIdx.x;
    int b   = bh >> 6;
    int h   = bh & 63;

    const float* xb = x + ((long)(b * CIN) * HH + h) * WW;
    for (int i = tid; i < CIN * WW; i += 256) {
        int cin = i >> 6, w = i & 63;
        xs[cin * 68 + w + 1] = xb[(long)cin * HH * WW + w];
    }
    if (tid < 64) {
        xs[tid * 68 + 0]  = 0.f;
        xs[tid * 68 + 65] = 0.f;
        xs[tid * 68 + 66] = 0.f;
        xs[tid * 68 + 67] = 0.f;
    }
    __syncthreads();

    int ocl = tid & 63;       // lane-consecutive -> conflict-free W
    int wb  = tid >> 6;       // warp-uniform     -> broadcast x
    int w0  = wb * 16;

    for (int p = 0; p < 4; p++) {
        int ocbase = p * 128;
        for (int i = tid; i < 128 * 192; i += 256) {
            int ol = i / 192, r = i % 192;
            int cin = r / 3, t = r % 3;
            float v = w_is[(long)(ocbase + ol) * 192 + r];
            if (t < 2) ws[(cin * 2 + t) * 128 + ol] = v;
        }
        __syncthreads();

        float acc0[16], acc1[16];
        float bb0 = b_is[ocbase + ocl];
        float bb1 = b_is[ocbase + ocl + 64];
#pragma unroll
        for (int j = 0; j < 16; j++) { acc0[j] = bb0; acc1[j] = bb1; }

        for (int cin = 0; cin < 64; cin++) {
            float w00 = ws[(cin * 2 + 0) * 128 + ocl];
            float w01 = ws[(cin * 2 + 1) * 128 + ocl];
            float w10 = ws[(cin * 2 + 0) * 128 + ocl + 64];
            float w11 = ws[(cin * 2 + 1) * 128 + ocl + 64];
            float xv[20];
            const float4* xp = reinterpret_cast<const float4*>(&xs[cin * 68 + w0]);
            *(float4*)&xv[0]  = xp[0];
            *(float4*)&xv[4]  = xp[1];
            *(float4*)&xv[8]  = xp[2];
            *(float4*)&xv[12] = xp[3];
            *(float4*)&xv[16] = xp[4];
#pragma unroll
            for (int j = 0; j < 16; j++) {
                acc0[j] = fmaf(xv[j],     w00, acc0[j]);
                acc0[j] = fmaf(xv[j + 1], w01, acc0[j]);
                acc1[j] = fmaf(xv[j],     w10, acc1[j]);
                acc1[j] = fmaf(xv[j + 1], w11, acc1[j]);
            }
        }

        float* z0 = &g_z[((long)bh * OC4 + ocbase + ocl)      * WW + w0];
        float* z1 = &g_z[((long)bh * OC4 + ocbase + ocl + 64) * WW + w0];
#pragma unroll
        for (int j = 0; j < 16; j += 4) {
            *(float4*)&z0[j] = make_float4(acc0[j], acc0[j+1], acc0[j+2], acc0[j+3]);
            *(float4*)&z1[j] = make_float4(acc1[j], acc1[j+1], acc1[j+2], acc1[j+3]);
        }
        __syncthreads();
    }
}

// ----------------------------------------------------------------------------
// Kernel 2: sequential row scan, FFMA2 + separated-tap1 accumulator.
// 8 CTAs per batch, 256 threads. l = tid&63 (conflict-free W), wb = tid>>6
// (broadcast h). Monotonic flag sync, double-buffered global h.
// ----------------------------------------------------------------------------
__global__ void __launch_bounds__(256)
scan_kernel(const float* __restrict__ w_ss,
            const float* __restrict__ b_ss,
            float* __restrict__ out)
{
    extern __shared__ float smem[];
    float* Wsm  = smem;                    // [(ic*3+t)][64 l]   24576 floats
    float* hs   = Wsm + 128 * 3 * 64;      // [128 ic][68]        8704 floats
    float* zbuf = hs + 128 * 68;           // [64 l][68 pad]      4352 floats
    float* cs   = zbuf + 64 * 68;          // [16 hcl][64 w]      1024 floats

    int tid  = threadIdx.x;
    int rank = blockIdx.x & 7;
    int b    = blockIdx.x >> 3;

    volatile int* flags = g_flag + b * 8;
    int base = flags[rank];                // own flag: race-free, launch-uniform

    // stage recurrent weights: Wsm[(ic*3+t)*64 + l] = w_ss[ocg(l)][ic][t]
    for (int i = tid; i < 128 * 3 * 64; i += 256) {
        int ic = i / 192, r = i % 192;
        int t = r >> 6, l = r & 63;
        int ocg = (l >> 4) * 128 + rank * 16 + (l & 15);
        Wsm[(ic * 3 + t) * 64 + l] = w_ss[((long)ocg * 128 + ic) * 3 + t];
    }
    // zero full hs (row 0 uses it directly: h0 = 0) and c state
    for (int i = tid; i < 128 * 68; i += 256) hs[i] = 0.f;
    for (int i = tid; i < 16 * 64; i += 256) cs[i] = 0.f;
    __syncthreads();

    int l  = tid & 63;        // gate g = l>>4, local hid = l&15
    int wb = tid >> 6;        // warp-uniform
    int w0 = wb * 16;
    int ocg = (l >> 4) * 128 + rank * 16 + (l & 15);
    ull bias2 = dup2(b_ss[ocg]);

    for (int row = 0; row < HH; row++) {
        int par1 = (row & 1) ^ 1;

        if (row > 0) {
            // load full h (parity row&1) into padded smem
            const float4* gh4 = (const float4*)&g_h[((long)(row & 1) * BB + b) * HID * WW];
            for (int i = tid; i < 2048; i += 256) {        // float4 index
                int ic = i >> 4, w = (i & 15) * 4;
                float4 v = gh4[i];
                float* d = &hs[ic * 68 + w + 1];
                d[0] = v.x; d[1] = v.y; d[2] = v.z; d[3] = v.w;
            }
            __syncthreads();
        }

        // acc = z_is + bias, packed over w pairs; T = tap1 accumulator
        ull acc[8], T[9];
        {
            const ulonglong2* zp = (const ulonglong2*)&g_z[(((long)b * HH + row) * OC4 + ocg) * WW + w0];
#pragma unroll
            for (int q = 0; q < 4; q++) {
                ulonglong2 v = zp[q];
                acc[2 * q]     = add2(v.x, bias2);
                acc[2 * q + 1] = add2(v.y, bias2);
            }
#pragma unroll
            for (int k = 0; k < 9; k++) T[k] = 0ull;
        }

        // recurrent conv: out[j] += hv[j]*w0 + hv[j+1]*w1 + hv[j+2]*w2
        // pairs: tap0 = A[k], tap2 = A[k+1], tap1 -> shifted accumulator T
#pragma unroll 2
        for (int ic = 0; ic < 128; ic++) {
            ull w0d = dup2(Wsm[(ic * 3 + 0) * 64 + l]);
            ull w1d = dup2(Wsm[(ic * 3 + 1) * 64 + l]);
            ull w2d = dup2(Wsm[(ic * 3 + 2) * 64 + l]);

            const float* hrow = &hs[ic * 68 + w0];   // broadcast within warp
            ull A[9];
            ulonglong2 q0 = *(const ulonglong2*)(hrow);
            ulonglong2 q1 = *(const ulonglong2*)(hrow + 4);
            ulonglong2 q2 = *(const ulonglong2*)(hrow + 8);
            ulonglong2 q3 = *(const ulonglong2*)(hrow + 12);
            A[0] = q0.x; A[1] = q0.y; A[2] = q1.x; A[3] = q1.y;
            A[4] = q2.x; A[5] = q2.y; A[6] = q3.x; A[7] = q3.y;
            A[8] = *(const ull*)(hrow + 16);

#pragma unroll
            for (int k = 0; k < 8; k++) {
                ffma2(acc[k], A[k],     w0d);
                ffma2(acc[k], A[k + 1], w2d);
                ffma2(T[k],   A[k],     w1d);
            }
            ffma2(T[8], A[8], w1d);
        }
        // recombine tap1: acc[k] += (hi T[k], lo T[k+1])
#pragma unroll
        for (int k = 0; k < 8; k++)
            acc[k] = add2(acc[k], pk2(hi32(T[k]), lo32(T[k + 1])));

#pragma unroll
        for (int k = 0; k < 8; k++)
            *(ull*)&zbuf[l * 68 + w0 + 2 * k] = acc[k];
        __syncthreads();

        // gate math: 1024 (hcl,w) elems, 4 per thread; write out + new h
        float* ghw = &g_h[((long)par1 * BB + b) * HID * WW];
#pragma unroll
        for (int k = 0; k < 4; k++) {
            int idx = tid + k * 256;
            int hcl = idx >> 6, w = idx & 63;
            float zi  = zbuf[(0  + hcl) * 68 + w];
            float zf  = zbuf[(16 + hcl) * 68 + w];
            float zo  = zbuf[(32 + hcl) * 68 + w];
            float zg2 = zbuf[(48 + hcl) * 68 + w];
            float ig = 1.f / (1.f + expf(-zi));
            float fg = 1.f / (1.f + expf(-zf));
            float og = 1.f / (1.f + expf(-zo));
            float gg = tanhf(zg2);
            float c = fg * cs[hcl * 64 + w] + ig * gg;
            cs[hcl * 64 + w] = c;
            float hv2 = og * tanhf(c);
            int ch = rank * 16 + hcl;
            out[(((long)b * HID + ch) * HH + row) * WW + w] = hv2;
            if (row < HH - 1) ghw[ch * WW + w] = hv2;
        }

        if (row < HH - 1) {
            __threadfence();
            __syncthreads();
            if (tid == 0) flags[rank] = base + row + 1;
            if (tid < 8) {
                while (flags[tid] < base + row + 1) { }
            }
            __threadfence();
            __syncthreads();
        }
    }
}

// ----------------------------------------------------------------------------
extern "C" void kernel_launch(void* const* d_in, const int* in_sizes, int n_in,
                              void* d_out, int out_size)
{
    (void)in_sizes; (void)n_in; (void)out_size;
    const float* x    = (const float*)d_in[0];
    const float* w_is = (const float*)d_in[1];
    const float* b_is = (const float*)d_in[2];
    const float* w_ss = (const float*)d_in[3];
    const float* b_ss = (const float*)d_in[4];
    float* out = (float*)d_out;

    const int conv_smem = (64 * 68 + 64 * 2 * 128) * 4;                      // 82944 B
    const int scan_smem = (128 * 3 * 64 + 128 * 68 + 64 * 68 + 16 * 64) * 4; // 154624 B

    cudaFuncSetAttribute(conv_in_kernel, cudaFuncAttributeMaxDynamicSharedMemorySize, conv_smem);
    cudaFuncSetAttribute(scan_kernel,    cudaFuncAttributeMaxDynamicSharedMemorySize, scan_smem);

    conv_in_kernel<<<BB * HH, 256, conv_smem>>>(x, w_is, b_is);
    scan_kernel<<<BB * 8, 256, scan_smem>>>(w_ss, b_ss, out);
}